// round 16
// baseline (speedup 1.0000x reference)
#include <cuda_runtime.h>
#include <cstdint>

// ---------------------------------------------------------------------------
// ConvLSTMCell (complex) via warp-level tf32 mma.sync implicit GEMM.
//   GEMM: D[65536 px, 384] = A[px, 2304] * B[2304, 384]
//   K = 9 taps x 256 ic;  N = 6 gate planes (i_r,i_i,o_r,o_i,c_r,c_i) x 64 oc
// f-gate is dead code in the reference -> skipped.
// R15: fragment loads via ldmatrix.m8n8.x4.b16 (tf32 8x4-f32 tile == 8x8-b16
//      matrix). LDS instr per warp per chunk: 96 -> 32.  B pack permutation
//      becomes identity (ldmatrix reads words positionally).
// ---------------------------------------------------------------------------

#define Bz    16
#define ICZ   256
#define HWP   4096
#define NOC   384
#define NCHUNKS 72        // K chunks of 32: c = q*9 + tap

// static scratch
__device__ __align__(128) float g_zpad[Bz * 66 * 66 * 256];   // NHWC padded, tf32-rounded
__device__ __align__(128) float g_w2p[NCHUNKS * 3 * 4096];    // weights, per (chunk,ntile)
__device__ float g_b2[NOC];                                   // biases
__device__ float g_gates[6 * Bz * 64 * HWP];                  // activated gates (~100MB)

// ---------------- helpers ---------------------------------------------------
__device__ __forceinline__ uint32_t smem_u32(const void* p) {
    uint32_t a;
    asm("{ .reg .u64 t; cvta.to.shared.u64 t, %1; cvt.u32.u64 %0, t; }" : "=r"(a) : "l"(p));
    return a;
}
__device__ __forceinline__ float tf32r(float x) {
    uint32_t u; asm("cvt.rna.tf32.f32 %0, %1;" : "=r"(u) : "f"(x));
    return __uint_as_float(u);
}
__device__ __forceinline__ void cp16ca(uint32_t s, const void* g) {
    asm volatile("cp.async.ca.shared.global [%0], [%1], 16;" :: "r"(s), "l"(g) : "memory");
}
__device__ __forceinline__ void cp16(uint32_t s, const void* g) {
    asm volatile("cp.async.cg.shared.global [%0], [%1], 16;" :: "r"(s), "l"(g) : "memory");
}
__device__ __forceinline__ void cp_commit() {
    asm volatile("cp.async.commit_group;" ::: "memory");
}
__device__ __forceinline__ void cp_wait0() {
    asm volatile("cp.async.wait_group 0;" ::: "memory");
}
__device__ __forceinline__ void ldmx4(uint32_t* r, uint32_t a) {
    asm volatile("ldmatrix.sync.aligned.m8n8.x4.shared.b16 {%0,%1,%2,%3}, [%4];"
                 : "=r"(r[0]), "=r"(r[1]), "=r"(r[2]), "=r"(r[3]) : "r"(a));
}
__device__ __forceinline__ void mma8(float* d, const uint32_t* a, const uint32_t* b) {
    asm volatile("mma.sync.aligned.m16n8k8.row.col.f32.tf32.tf32.f32 "
                 "{%0,%1,%2,%3}, {%4,%5,%6,%7}, {%8,%9}, {%0,%1,%2,%3};"
                 : "+f"(d[0]), "+f"(d[1]), "+f"(d[2]), "+f"(d[3])
                 : "r"(a[0]), "r"(a[1]), "r"(a[2]), "r"(a[3]), "r"(b[0]), "r"(b[1]));
}
__device__ __forceinline__ float sigm(float v)  { return __fdividef(1.0f, 1.0f + __expf(-v)); }
__device__ __forceinline__ float tanh_(float v) { return 1.0f - __fdividef(2.0f, 1.0f + __expf(2.0f * v)); }

// ---------------------------------------------------------------------------
// Kernel 1a: zero the padded border (NHWC).  border pixels = 260 per batch.
// ---------------------------------------------------------------------------
__global__ void zpad_border() {
    int idx = blockIdx.x * blockDim.x + threadIdx.x;
    if (idx >= Bz * 260 * 256) return;
    int b = idx / (260 * 256);
    int r = idx - b * (260 * 256);
    int bp = r >> 8, ic = r & 255;
    int yy, xx;
    if (bp < 66)       { yy = 0;  xx = bp; }
    else if (bp < 132) { yy = 65; xx = bp - 66; }
    else { int t = bp - 132; yy = 1 + (t >> 1); xx = (t & 1) * 65; }
    g_zpad[((size_t)(b * 66 + yy) * 66 + xx) * 256 + ic] = 0.0f;
}

// ---------------------------------------------------------------------------
// Kernel 1b: interior transpose NCHW -> NHWC, tf32-rounded.
// z channel order: [xr(64) | hr(64) | xi(64) | hi(64)].
// grid (16 tiles = 2 xt * 8 ict, 64 y, 16 b), block (32, 8).
// ---------------------------------------------------------------------------
__global__ void zpad_interior(const float* __restrict__ x, const float* __restrict__ h) {
    __shared__ float s[32][33];
    const int b   = blockIdx.z;
    const int y   = blockIdx.y;                 // 0..63
    const int xt  = blockIdx.x & 1;
    const int ict = blockIdx.x >> 1;            // 0..7
    const int tx = threadIdx.x, ty = threadIdx.y;
    const int x0  = xt * 32;
    const int ic0 = ict * 32;
    const float* src; int chbase;
    if (ic0 < 64)       { src = x; chbase = ic0;       }
    else if (ic0 < 128) { src = h; chbase = ic0 - 64;  }
    else if (ic0 < 192) { src = x; chbase = ic0 - 64;  }
    else                { src = h; chbase = ic0 - 128; }
    #pragma unroll
    for (int k = 0; k < 4; ++k) {
        int icl = ty + k * 8;
        s[icl][tx] = tf32r(src[(size_t)(b * 128 + chbase + icl) * HWP + y * 64 + x0 + tx]);
    }
    __syncthreads();
    float* dst = g_zpad + ((size_t)(b * 66 + y + 1) * 66 + x0 + 1) * 256 + ic0;
    #pragma unroll
    for (int k = 0; k < 4; ++k) {
        int xl = ty + k * 8;
        dst[(size_t)xl * 256 + tx] = s[tx][xl];
    }
}

// ---------------------------------------------------------------------------
// Kernel 2: pack weights into per-(chunk, ntile) smem images (4096 floats).
// chunk c: q = c/9 (ic block), tap = c%9.  Image float f:
//   g=f>>10; n_local=(f>>3)&127; w=f&7;
//   ic = q*32 + g*8 + w   (identity within-row order, required by ldmatrix)
//   n = ntile*128 + n_local
// n = plane*64+oc, planes (i_r,i_i,o_r,o_i,c_r,c_i); real: [Wr|-Wi] imag: [Wi|Wr].
// ---------------------------------------------------------------------------
__global__ void pack_w(const float* __restrict__ Wri, const float* __restrict__ Wii,
                       const float* __restrict__ Wro, const float* __restrict__ Wio,
                       const float* __restrict__ Wrc, const float* __restrict__ Wic,
                       const float* __restrict__ bri, const float* __restrict__ bii,
                       const float* __restrict__ bro, const float* __restrict__ bio,
                       const float* __restrict__ brc, const float* __restrict__ bic) {
    int idx = blockIdx.x * blockDim.x + threadIdx.x;
    if (idx < NOC) {
        int plane = idx >> 6, oc = idx & 63;
        int g = plane >> 1, part = plane & 1;
        const float* bp = part ? (g == 0 ? bii : (g == 1 ? bio : bic))
                               : (g == 0 ? bri : (g == 1 ? bro : brc));
        g_b2[idx] = bp[oc];
    }
    if (idx >= NCHUNKS * 3 * 4096) return;
    int chunk = idx / 12288;
    int rem   = idx - chunk * 12288;
    int ntile = rem >> 12;
    int f     = rem & 4095;
    int g  = f >> 10;
    int r2 = f & 1023;
    int nl = r2 >> 3;
    int w  = r2 & 7;
    int q   = chunk / 9;
    int tap = chunk - q * 9;
    int ic  = q * 32 + g * 8 + w;                 // identity order
    int n   = ntile * 128 + nl;                   // 0..383
    int plane = n >> 6, oc = n & 63;
    int gate = plane >> 1, part = plane & 1;
    const float* Wr = (gate == 0) ? Wri : (gate == 1) ? Wro : Wrc;
    const float* Wi = (gate == 0) ? Wii : (gate == 1) ? Wio : Wic;
    float v;
    if (ic < 128) v = part ? Wi[(oc * 128 + ic) * 9 + tap] : Wr[(oc * 128 + ic) * 9 + tap];
    else {
        int icc = ic - 128;
        v = part ? Wr[(oc * 128 + icc) * 9 + tap] : -Wi[(oc * 128 + icc) * 9 + tap];
    }
    g_w2p[idx] = tf32r(v);
}

// ---------------------------------------------------------------------------
// Kernel 3: tf32 mma.sync GEMM conv.
// CTA 128 thr (4 warps), tile M=128 N=128, warp tile 64x64, K chunks of 32,
// cp.async double-buffered smem.  A smem: [128 px][36 words] (32 data + 4 pad).
// Fragments via ldmatrix.x4 (tf32-as-b16 trick).
// ---------------------------------------------------------------------------
#define A_WORDS 4608             // 128 * 36
#define B_WORDS 4096             // 4 g * 128 n * 8 words
#define STG_WORDS 8704
#define SMEM_BYTES (2 * STG_WORDS * 4)

__global__ void __launch_bounds__(128, 2)
conv_mma() {
    extern __shared__ float smem[];
    const uint32_t sbase = smem_u32(smem);
    const int tid  = threadIdx.x;
    const int lane = tid & 31, wid = tid >> 5;
    const int warp_m = wid & 1, warp_n = wid >> 1;
    const int ntile = blockIdx.x;                 // 0..2
    const int mtile = blockIdx.y;                 // 0..511
    const int b  = mtile >> 5;
    const int y0 = (mtile & 31) << 1;
    const float* zb = g_zpad + (size_t)b * (66 * 66 * 256);

    float acc[4][8][4];
    #pragma unroll
    for (int mt = 0; mt < 4; ++mt)
        #pragma unroll
        for (int nt = 0; nt < 8; ++nt)
            #pragma unroll
            for (int k = 0; k < 4; ++k) acc[mt][nt][k] = 0.0f;

    // A-gather mapping: 8 lanes (l8) cover one pixel's 32 floats (128B line).
    const int pxq = tid >> 3;                     // 0..15 : pixel-within-group
    const int l8  = tid & 7;                      // 0..7  : 16B slot within line
    const uint32_t a_dst0 = (uint32_t)pxq * 144 + (uint32_t)l8 * 16;

    // ldmatrix lane-derived address constants
    const int arow  = (lane & 7) + ((lane & 8) ? 8 : 0);     // row in 16-row tile
    const uint32_t axtra = (lane & 16) ? 16u : 0u;           // k-half byte offset
    const int bn7   = lane & 7;
    const int bnt1  = (lane & 16) ? 1 : 0;                   // second nt of pair
    const uint32_t bxtra = (lane & 8) ? 16u : 0u;            // k-half byte offset

    // ---- chunk loader (cp.async) ----
    auto load_chunk = [&](int c, int stage) {
        const int q = c / 9;                      // ic block 0..7
        const int tap = c - q * 9;
        const int ky = tap / 3, kx = tap - ky * 3;
        const float* row0 = zb + (size_t)((y0 + ky) * 66 + kx) * 256 + q * 32 + l8 * 4;
        const float* row1 = row0 + 66 * 256;
        const uint32_t as = sbase + (uint32_t)stage * (STG_WORDS * 4) + a_dst0;
        #pragma unroll
        for (int j = 0; j < 8; ++j) {
            // pixel p = j*16 + pxq ; rows split at p=64 (j<4 -> row0)
            const float* src = ((j < 4) ? row0 : row1) + (size_t)((j & 3) * 16 + pxq) * 256;
            cp16ca(as + (uint32_t)j * 2304, src);            // 16 px * 144 B
        }
        const float4* bsrc = reinterpret_cast<const float4*>(
                                 g_w2p + ((size_t)c * 3 + ntile) * 4096) + tid;
        const uint32_t bs = sbase + (uint32_t)stage * (STG_WORDS * 4) + A_WORDS * 4 + tid * 16;
        #pragma unroll
        for (int j = 0; j < 8; ++j)
            cp16(bs + (uint32_t)j * 2048, bsrc + j * 128);
        cp_commit();
    };

    // ---- compute one chunk from smem stage ----
    auto compute = [&](int stage) {
        const uint32_t as = sbase + (uint32_t)stage * (STG_WORDS * 4);
        const uint32_t bs = as + A_WORDS * 4;
        #pragma unroll
        for (int g = 0; g < 4; ++g) {
            uint32_t af[4][4];
            #pragma unroll
            for (int mt = 0; mt < 4; ++mt) {
                uint32_t addr = as + (uint32_t)((warp_m * 64 + mt * 16 + arow) * 144)
                                   + (uint32_t)(g * 32) + axtra;
                ldmx4(af[mt], addr);
            }
            uint32_t bf[8][2];
            #pragma unroll
            for (int p = 0; p < 4; ++p) {
                int n = warp_n * 64 + (p * 2 + bnt1) * 8 + bn7;
                uint32_t addr = bs + (uint32_t)((g * 128 + n) * 32) + bxtra;
                uint32_t t[4];
                ldmx4(t, addr);
                bf[2 * p][0] = t[0]; bf[2 * p][1] = t[1];
                bf[2 * p + 1][0] = t[2]; bf[2 * p + 1][1] = t[3];
            }
            #pragma unroll
            for (int mt = 0; mt < 4; ++mt)
                #pragma unroll
                for (int nt = 0; nt < 8; ++nt)
                    mma8(acc[mt][nt], af[mt], bf[nt]);
        }
    };

    load_chunk(0, 0);
    cp_wait0();
    __syncthreads();

    for (int c = 0; c < NCHUNKS; ++c) {
        const int s = c & 1;
        if (c + 1 < NCHUNKS) load_chunk(c + 1, s ^ 1);
        compute(s);
        if (c + 1 < NCHUNKS) cp_wait0();
        __syncthreads();
    }

    // ---- epilogue: bias + activation -> g_gates[plane][b][oc][pos] ----
    const int basepos = (mtile & 31) * 128;
    const int r0 = warp_m * 64 + (lane >> 2);
    const int c0 = ntile * 128 + warp_n * 64 + 2 * (lane & 3);
    #pragma unroll
    for (int nt = 0; nt < 8; ++nt) {
        const int n0 = c0 + nt * 8;
        const float b0v = g_b2[n0], b1v = g_b2[n0 + 1];
        const int pl0 = n0 >> 6, oc0 = n0 & 63;
        const int pl1 = (n0 + 1) >> 6, oc1 = (n0 + 1) & 63;
        float* g0 = g_gates + (size_t)(pl0 * Bz + b) * 262144 + oc0 * HWP + basepos;
        float* g1 = g_gates + (size_t)(pl1 * Bz + b) * 262144 + oc1 * HWP + basepos;
        #pragma unroll
        for (int mt = 0; mt < 4; ++mt) {
            #pragma unroll
            for (int k = 0; k < 4; ++k) {
                const int mrow = r0 + mt * 16 + ((k & 2) ? 8 : 0);
                float v = acc[mt][nt][k] + ((k & 1) ? b1v : b0v);
                const int pl = (k & 1) ? pl1 : pl0;
                v = (pl >= 4) ? tanh_(v) : sigm(v);
                ((k & 1) ? g1 : g0)[mrow] = v;
            }
        }
    }
}

// ---------------------------------------------------------------------------
// Kernel 4: elementwise cell update
// ---------------------------------------------------------------------------
__global__ void ewise(const float* __restrict__ x, const float* __restrict__ c_prev,
                      float* __restrict__ out) {
    int idx = blockIdx.x * blockDim.x + threadIdx.x;
    if (idx >= Bz * 64 * HWP) return;
    int b   = idx >> 18;
    int r   = idx & 262143;
    int ch  = r >> 12;
    int pos = r & 4095;
    int base  = (b * 128 + ch) * HWP + pos;
    int basei = base + 64 * HWP;

    float xr = x[base],      xi = x[basei];
    float cr = c_prev[base], ci = c_prev[basei];

    const int GP = Bz * 64 * HWP;
    float i_r  = g_gates[idx];
    float i_i  = g_gates[GP + idx];
    float o_r  = g_gates[2 * GP + idx];
    float o_i  = g_gates[3 * GP + idx];
    float ct_r = g_gates[4 * GP + idx];
    float ct_i = g_gates[5 * GP + idx];

    float cnr = xr * cr - xi * ci + i_r * ct_r - i_i * ct_i;
    float cni = xr * ci + xi * cr + i_r * ct_i + i_i * ct_r;
    float tr = tanhf(cnr), ti = tanhf(cni);
    float hr = o_r * tr - o_i * ti;
    float hi = o_r * ti + o_i * tr;

    const int HTOT = Bz * 128 * HWP;
    out[base]          = hr;
    out[basei]         = hi;
    out[HTOT + base]   = cnr;
    out[HTOT + basei]  = cni;
}

// ---------------------------------------------------------------------------
extern "C" void kernel_launch(void* const* d_in, const int* in_sizes, int n_in,
                              void* d_out, int out_size) {
    const float* x      = (const float*)d_in[0];
    const float* h_prev = (const float*)d_in[1];
    const float* c_prev = (const float*)d_in[2];
    const float* Wr_i = (const float*)d_in[3];
    const float* Wi_i = (const float*)d_in[4];
    const float* br_i = (const float*)d_in[5];
    const float* bi_i = (const float*)d_in[6];
    // d_in[7..10] = f gate (unused by the reference output)
    const float* Wr_o = (const float*)d_in[11];
    const float* Wi_o = (const float*)d_in[12];
    const float* br_o = (const float*)d_in[13];
    const float* bi_o = (const float*)d_in[14];
    const float* Wr_c = (const float*)d_in[15];
    const float* Wi_c = (const float*)d_in[16];
    const float* br_c = (const float*)d_in[17];
    const float* bi_c = (const float*)d_in[18];

    cudaFuncSetAttribute(conv_mma, cudaFuncAttributeMaxDynamicSharedMemorySize, SMEM_BYTES);

    const int NB = Bz * 260 * 256;
    zpad_border<<<(NB + 255) / 256, 256>>>();
    zpad_interior<<<dim3(16, 64, 16), dim3(32, 8)>>>(x, h_prev);

    const int NW = NCHUNKS * 3 * 4096;
    pack_w<<<(NW + 255) / 256, 256>>>(Wr_i, Wi_i, Wr_o, Wi_o, Wr_c, Wi_c,
                                      br_i, bi_i, br_o, bi_o, br_c, bi_c);

    conv_mma<<<dim3(3, 512), 128, SMEM_BYTES>>>();

    const int NE = Bz * 64 * HWP;
    ewise<<<NE / 256, 256>>>(x, c_prev, (float*)d_out);
}

// round 17
// speedup vs baseline: 1.0758x; 1.0758x over previous
#include <cuda_runtime.h>
#include <cstdint>

// ---------------------------------------------------------------------------
// ConvLSTMCell (complex) via warp-level tf32 mma.sync implicit GEMM.
//   GEMM: D[65536 px, 384] = A[px, 2304] * B[2304, 384]
//   K = 9 taps x 256 ic;  N = 6 gate planes (i_r,i_i,o_r,o_i,c_r,c_i) x 64 oc
// f-gate is dead code in the reference -> skipped.
// R17: revert R15's ldmatrix (regressed: more L1 wavefronts). Back to R14
//      LDS.32/LDS.64 fragment loads, PLUS intra-chunk fragment double-
//      buffering: prefetch k8-group g+1's fragments while g's 32 HMMAs drain.
// ---------------------------------------------------------------------------

#define Bz    16
#define ICZ   256
#define HWP   4096
#define NOC   384
#define NCHUNKS 72        // K chunks of 32: c = q*9 + tap

// static scratch
__device__ __align__(128) float g_zpad[Bz * 66 * 66 * 256];   // NHWC padded, tf32-rounded
__device__ __align__(128) float g_w2p[NCHUNKS * 3 * 4096];    // weights, per (chunk,ntile)
__device__ float g_b2[NOC];                                   // biases
__device__ float g_gates[6 * Bz * 64 * HWP];                  // activated gates (~100MB)

// ---------------- helpers ---------------------------------------------------
__device__ __forceinline__ uint32_t smem_u32(const void* p) {
    uint32_t a;
    asm("{ .reg .u64 t; cvta.to.shared.u64 t, %1; cvt.u32.u64 %0, t; }" : "=r"(a) : "l"(p));
    return a;
}
__device__ __forceinline__ float tf32r(float x) {
    uint32_t u; asm("cvt.rna.tf32.f32 %0, %1;" : "=r"(u) : "f"(x));
    return __uint_as_float(u);
}
__device__ __forceinline__ void cp16ca(uint32_t s, const void* g) {
    asm volatile("cp.async.ca.shared.global [%0], [%1], 16;" :: "r"(s), "l"(g) : "memory");
}
__device__ __forceinline__ void cp16(uint32_t s, const void* g) {
    asm volatile("cp.async.cg.shared.global [%0], [%1], 16;" :: "r"(s), "l"(g) : "memory");
}
__device__ __forceinline__ void cp_commit() {
    asm volatile("cp.async.commit_group;" ::: "memory");
}
__device__ __forceinline__ void cp_wait0() {
    asm volatile("cp.async.wait_group 0;" ::: "memory");
}
__device__ __forceinline__ void lds32(uint32_t& r, uint32_t a) {
    asm volatile("ld.shared.b32 %0, [%1];" : "=r"(r) : "r"(a));
}
__device__ __forceinline__ void lds64(uint32_t* r, uint32_t a) {
    asm volatile("ld.shared.v2.b32 {%0,%1}, [%2];" : "=r"(r[0]), "=r"(r[1]) : "r"(a));
}
__device__ __forceinline__ void mma8(float* d, const uint32_t* a, const uint32_t* b) {
    asm volatile("mma.sync.aligned.m16n8k8.row.col.f32.tf32.tf32.f32 "
                 "{%0,%1,%2,%3}, {%4,%5,%6,%7}, {%8,%9}, {%0,%1,%2,%3};"
                 : "+f"(d[0]), "+f"(d[1]), "+f"(d[2]), "+f"(d[3])
                 : "r"(a[0]), "r"(a[1]), "r"(a[2]), "r"(a[3]), "r"(b[0]), "r"(b[1]));
}
__device__ __forceinline__ float sigm(float v)  { return __fdividef(1.0f, 1.0f + __expf(-v)); }
__device__ __forceinline__ float tanh_(float v) { return 1.0f - __fdividef(2.0f, 1.0f + __expf(2.0f * v)); }

// ---------------------------------------------------------------------------
// Kernel 1a: zero the padded border (NHWC).  border pixels = 260 per batch.
// ---------------------------------------------------------------------------
__global__ void zpad_border() {
    int idx = blockIdx.x * blockDim.x + threadIdx.x;
    if (idx >= Bz * 260 * 256) return;
    int b = idx / (260 * 256);
    int r = idx - b * (260 * 256);
    int bp = r >> 8, ic = r & 255;
    int yy, xx;
    if (bp < 66)       { yy = 0;  xx = bp; }
    else if (bp < 132) { yy = 65; xx = bp - 66; }
    else { int t = bp - 132; yy = 1 + (t >> 1); xx = (t & 1) * 65; }
    g_zpad[((size_t)(b * 66 + yy) * 66 + xx) * 256 + ic] = 0.0f;
}

// ---------------------------------------------------------------------------
// Kernel 1b: interior transpose NCHW -> NHWC, tf32-rounded.
// z channel order: [xr(64) | hr(64) | xi(64) | hi(64)].
// grid (16 tiles = 2 xt * 8 ict, 64 y, 16 b), block (32, 8).
// ---------------------------------------------------------------------------
__global__ void zpad_interior(const float* __restrict__ x, const float* __restrict__ h) {
    __shared__ float s[32][33];
    const int b   = blockIdx.z;
    const int y   = blockIdx.y;                 // 0..63
    const int xt  = blockIdx.x & 1;
    const int ict = blockIdx.x >> 1;            // 0..7
    const int tx = threadIdx.x, ty = threadIdx.y;
    const int x0  = xt * 32;
    const int ic0 = ict * 32;
    const float* src; int chbase;
    if (ic0 < 64)       { src = x; chbase = ic0;       }
    else if (ic0 < 128) { src = h; chbase = ic0 - 64;  }
    else if (ic0 < 192) { src = x; chbase = ic0 - 64;  }
    else                { src = h; chbase = ic0 - 128; }
    #pragma unroll
    for (int k = 0; k < 4; ++k) {
        int icl = ty + k * 8;
        s[icl][tx] = tf32r(src[(size_t)(b * 128 + chbase + icl) * HWP + y * 64 + x0 + tx]);
    }
    __syncthreads();
    float* dst = g_zpad + ((size_t)(b * 66 + y + 1) * 66 + x0 + 1) * 256 + ic0;
    #pragma unroll
    for (int k = 0; k < 4; ++k) {
        int xl = ty + k * 8;
        dst[(size_t)xl * 256 + tx] = s[tx][xl];
    }
}

// ---------------------------------------------------------------------------
// Kernel 2: pack weights into per-(chunk, ntile) smem images (4096 floats).
// chunk c: q = c/9 (ic block), tap = c%9.  Image float f:
//   g=f>>10; n_local=(f>>3)&127; w=f&7; cc=w>>1; h=w&1;
//   ic = q*32 + g*8 + cc + 4h;  n = ntile*128 + n_local
// n = plane*64+oc, planes (i_r,i_i,o_r,o_i,c_r,c_i); real: [Wr|-Wi] imag: [Wi|Wr].
// ---------------------------------------------------------------------------
__global__ void pack_w(const float* __restrict__ Wri, const float* __restrict__ Wii,
                       const float* __restrict__ Wro, const float* __restrict__ Wio,
                       const float* __restrict__ Wrc, const float* __restrict__ Wic,
                       const float* __restrict__ bri, const float* __restrict__ bii,
                       const float* __restrict__ bro, const float* __restrict__ bio,
                       const float* __restrict__ brc, const float* __restrict__ bic) {
    int idx = blockIdx.x * blockDim.x + threadIdx.x;
    if (idx < NOC) {
        int plane = idx >> 6, oc = idx & 63;
        int g = plane >> 1, part = plane & 1;
        const float* bp = part ? (g == 0 ? bii : (g == 1 ? bio : bic))
                               : (g == 0 ? bri : (g == 1 ? bro : brc));
        g_b2[idx] = bp[oc];
    }
    if (idx >= NCHUNKS * 3 * 4096) return;
    int chunk = idx / 12288;
    int rem   = idx - chunk * 12288;
    int ntile = rem >> 12;
    int f     = rem & 4095;
    int g  = f >> 10;
    int r2 = f & 1023;
    int nl = r2 >> 3;
    int w  = r2 & 7;
    int cc = w >> 1, h = w & 1;
    int q   = chunk / 9;
    int tap = chunk - q * 9;
    int ic  = q * 32 + g * 8 + cc + 4 * h;        // 0..255
    int n   = ntile * 128 + nl;                   // 0..383
    int plane = n >> 6, oc = n & 63;
    int gate = plane >> 1, part = plane & 1;
    const float* Wr = (gate == 0) ? Wri : (gate == 1) ? Wro : Wrc;
    const float* Wi = (gate == 0) ? Wii : (gate == 1) ? Wio : Wic;
    float v;
    if (ic < 128) v = part ? Wi[(oc * 128 + ic) * 9 + tap] : Wr[(oc * 128 + ic) * 9 + tap];
    else {
        int icc = ic - 128;
        v = part ? Wr[(oc * 128 + icc) * 9 + tap] : -Wi[(oc * 128 + icc) * 9 + tap];
    }
    g_w2p[idx] = tf32r(v);
}

// ---------------------------------------------------------------------------
// Kernel 3: tf32 mma.sync GEMM conv.
// CTA 128 thr (4 warps), tile M=128 N=128, warp tile 64x64, K chunks of 32,
// cp.async double-buffered smem.  A smem: [128 px][36 words] (32 data + 4 pad).
// A gather: 8 lanes x 16B cover one pixel line -> 4 lines per warp LDGSTS.
// Compute: fragment double-buffering across the 4 k8-groups.
// ---------------------------------------------------------------------------
#define A_WORDS 4608             // 128 * 36
#define B_WORDS 4096             // 4 g * 128 n * 8 words
#define STG_WORDS 8704
#define SMEM_BYTES (2 * STG_WORDS * 4)

__global__ void __launch_bounds__(128, 2)
conv_mma() {
    extern __shared__ float smem[];
    const uint32_t sbase = smem_u32(smem);
    const int tid  = threadIdx.x;
    const int lane = tid & 31, wid = tid >> 5;
    const int warp_m = wid & 1, warp_n = wid >> 1;
    const int ntile = blockIdx.x;                 // 0..2
    const int mtile = blockIdx.y;                 // 0..511
    const int b  = mtile >> 5;
    const int y0 = (mtile & 31) << 1;
    const float* zb = g_zpad + (size_t)b * (66 * 66 * 256);

    float acc[4][8][4];
    #pragma unroll
    for (int mt = 0; mt < 4; ++mt)
        #pragma unroll
        for (int nt = 0; nt < 8; ++nt)
            #pragma unroll
            for (int k = 0; k < 4; ++k) acc[mt][nt][k] = 0.0f;

    // A-gather mapping: 8 lanes (l8) cover one pixel's 32 floats (128B line).
    const int pxq = tid >> 3;                     // 0..15 : pixel-within-group
    const int l8  = tid & 7;                      // 0..7  : 16B slot within line
    const uint32_t a_dst0 = (uint32_t)pxq * 144 + (uint32_t)l8 * 16;

    // ---- chunk loader (cp.async) ----
    auto load_chunk = [&](int c, int stage) {
        const int q = c / 9;                      // ic block 0..7
        const int tap = c - q * 9;
        const int ky = tap / 3, kx = tap - ky * 3;
        const float* row0 = zb + (size_t)((y0 + ky) * 66 + kx) * 256 + q * 32 + l8 * 4;
        const float* row1 = row0 + 66 * 256;
        const uint32_t as = sbase + (uint32_t)stage * (STG_WORDS * 4) + a_dst0;
        #pragma unroll
        for (int j = 0; j < 8; ++j) {
            // pixel p = j*16 + pxq ; rows split at p=64 (j<4 -> row0)
            const float* src = ((j < 4) ? row0 : row1) + (size_t)((j & 3) * 16 + pxq) * 256;
            cp16ca(as + (uint32_t)j * 2304, src);            // 16 px * 144 B
        }
        const float4* bsrc = reinterpret_cast<const float4*>(
                                 g_w2p + ((size_t)c * 3 + ntile) * 4096) + tid;
        const uint32_t bs = sbase + (uint32_t)stage * (STG_WORDS * 4) + A_WORDS * 4 + tid * 16;
        #pragma unroll
        for (int j = 0; j < 8; ++j)
            cp16(bs + (uint32_t)j * 2048, bsrc + j * 128);
        cp_commit();
    };

    const int rl = lane >> 2, cl = lane & 3;

    // fragment load macro: k8-group G from stage base AS/BS into AF/BF
#define LOAD_FRAGS(AS, BS, G, AF, BF)                                          \
    do {                                                                       \
        _Pragma("unroll")                                                      \
        for (int mt = 0; mt < 4; ++mt) {                                       \
            uint32_t r0 = (AS) + (uint32_t)(((warp_m * 64 + mt * 16 + rl) * 36 \
                                             + (G) * 8 + cl) * 4);             \
            lds32(AF[mt][0], r0);                                              \
            lds32(AF[mt][1], r0 + 8 * 36 * 4);                                 \
            lds32(AF[mt][2], r0 + 16);                                         \
            lds32(AF[mt][3], r0 + 8 * 36 * 4 + 16);                            \
        }                                                                      \
        _Pragma("unroll")                                                      \
        for (int nt = 0; nt < 8; ++nt) {                                       \
            int n = warp_n * 64 + nt * 8 + rl;                                 \
            lds64(BF[nt], (BS) + (uint32_t)((((G) * 128 + n) * 8 + cl * 2) * 4)); \
        }                                                                      \
    } while (0)

#define MMA_ALL(AF, BF)                                                        \
    do {                                                                       \
        _Pragma("unroll")                                                      \
        for (int mt = 0; mt < 4; ++mt)                                         \
            _Pragma("unroll")                                                  \
            for (int nt = 0; nt < 8; ++nt)                                     \
                mma8(acc[mt][nt], AF[mt], BF[nt]);                             \
    } while (0)

    // ---- compute one chunk from smem stage (frag double-buffered) ----
    auto compute = [&](int stage) {
        const uint32_t as = sbase + (uint32_t)stage * (STG_WORDS * 4);
        const uint32_t bs = as + A_WORDS * 4;
        uint32_t af0[4][4], af1[4][4], bf0[8][2], bf1[8][2];
        LOAD_FRAGS(as, bs, 0, af0, bf0);
        LOAD_FRAGS(as, bs, 1, af1, bf1);
        MMA_ALL(af0, bf0);
        LOAD_FRAGS(as, bs, 2, af0, bf0);
        MMA_ALL(af1, bf1);
        LOAD_FRAGS(as, bs, 3, af1, bf1);
        MMA_ALL(af0, bf0);
        MMA_ALL(af1, bf1);
    };

    load_chunk(0, 0);
    cp_wait0();
    __syncthreads();

    for (int c = 0; c < NCHUNKS; ++c) {
        const int s = c & 1;
        if (c + 1 < NCHUNKS) load_chunk(c + 1, s ^ 1);
        compute(s);
        if (c + 1 < NCHUNKS) cp_wait0();
        __syncthreads();
    }

    // ---- epilogue: bias + activation -> g_gates[plane][b][oc][pos] ----
    const int basepos = (mtile & 31) * 128;
    const int r0 = warp_m * 64 + (lane >> 2);
    const int c0 = ntile * 128 + warp_n * 64 + 2 * (lane & 3);
    #pragma unroll
    for (int nt = 0; nt < 8; ++nt) {
        const int n0 = c0 + nt * 8;
        const float b0v = g_b2[n0], b1v = g_b2[n0 + 1];
        const int pl0 = n0 >> 6, oc0 = n0 & 63;
        const int pl1 = (n0 + 1) >> 6, oc1 = (n0 + 1) & 63;
        float* g0 = g_gates + (size_t)(pl0 * Bz + b) * 262144 + oc0 * HWP + basepos;
        float* g1 = g_gates + (size_t)(pl1 * Bz + b) * 262144 + oc1 * HWP + basepos;
        #pragma unroll
        for (int mt = 0; mt < 4; ++mt) {
            #pragma unroll
            for (int k = 0; k < 4; ++k) {
                const int mrow = r0 + mt * 16 + ((k & 2) ? 8 : 0);
                float v = acc[mt][nt][k] + ((k & 1) ? b1v : b0v);
                const int pl = (k & 1) ? pl1 : pl0;
                v = (pl >= 4) ? tanh_(v) : sigm(v);
                ((k & 1) ? g1 : g0)[mrow] = v;
            }
        }
    }
}

// ---------------------------------------------------------------------------
// Kernel 4: elementwise cell update
// ---------------------------------------------------------------------------
__global__ void ewise(const float* __restrict__ x, const float* __restrict__ c_prev,
                      float* __restrict__ out) {
    int idx = blockIdx.x * blockDim.x + threadIdx.x;
    if (idx >= Bz * 64 * HWP) return;
    int b   = idx >> 18;
    int r   = idx & 262143;
    int ch  = r >> 12;
    int pos = r & 4095;
    int base  = (b * 128 + ch) * HWP + pos;
    int basei = base + 64 * HWP;

    float xr = x[base],      xi = x[basei];
    float cr = c_prev[base], ci = c_prev[basei];

    const int GP = Bz * 64 * HWP;
    float i_r  = g_gates[idx];
    float i_i  = g_gates[GP + idx];
    float o_r  = g_gates[2 * GP + idx];
    float o_i  = g_gates[3 * GP + idx];
    float ct_r = g_gates[4 * GP + idx];
    float ct_i = g_gates[5 * GP + idx];

    float cnr = xr * cr - xi * ci + i_r * ct_r - i_i * ct_i;
    float cni = xr * ci + xi * cr + i_r * ct_i + i_i * ct_r;
    float tr = tanhf(cnr), ti = tanhf(cni);
    float hr = o_r * tr - o_i * ti;
    float hi = o_r * ti + o_i * tr;

    const int HTOT = Bz * 128 * HWP;
    out[base]          = hr;
    out[basei]         = hi;
    out[HTOT + base]   = cnr;
    out[HTOT + basei]  = cni;
}

// ---------------------------------------------------------------------------
extern "C" void kernel_launch(void* const* d_in, const int* in_sizes, int n_in,
                              void* d_out, int out_size) {
    const float* x      = (const float*)d_in[0];
    const float* h_prev = (const float*)d_in[1];
    const float* c_prev = (const float*)d_in[2];
    const float* Wr_i = (const float*)d_in[3];
    const float* Wi_i = (const float*)d_in[4];
    const float* br_i = (const float*)d_in[5];
    const float* bi_i = (const float*)d_in[6];
    // d_in[7..10] = f gate (unused by the reference output)
    const float* Wr_o = (const float*)d_in[11];
    const float* Wi_o = (const float*)d_in[12];
    const float* br_o = (const float*)d_in[13];
    const float* bi_o = (const float*)d_in[14];
    const float* Wr_c = (const float*)d_in[15];
    const float* Wi_c = (const float*)d_in[16];
    const float* br_c = (const float*)d_in[17];
    const float* bi_c = (const float*)d_in[18];

    cudaFuncSetAttribute(conv_mma, cudaFuncAttributeMaxDynamicSharedMemorySize, SMEM_BYTES);

    const int NB = Bz * 260 * 256;
    zpad_border<<<(NB + 255) / 256, 256>>>();
    zpad_interior<<<dim3(16, 64, 16), dim3(32, 8)>>>(x, h_prev);

    const int NW = NCHUNKS * 3 * 4096;
    pack_w<<<(NW + 255) / 256, 256>>>(Wr_i, Wi_i, Wr_o, Wi_o, Wr_c, Wi_c,
                                      br_i, bi_i, br_o, bi_o, br_c, bi_c);

    conv_mma<<<dim3(3, 512), 128, SMEM_BYTES>>>();

    const int NE = Bz * 64 * HWP;
    ewise<<<NE / 256, 256>>>(x, c_prev, (float*)d_out);
}